// round 3
// baseline (speedup 1.0000x reference)
#include <cuda_runtime.h>
#include <math.h>

#define NKNOT 1024
#define NW    1020   // NUM_KNOTS - DEGREE - 1

// fp32 images of +/-pi (== np.linspace endpoints after float32 cast)
#define T_LO (-3.14159274101257324218750f)
#define T_HI ( 3.14159274101257324218750f)
// 1023/(2*pi), correctly rounded fp32
#define INV_H 162.81578063964843750f
// pi * 1023/(2*pi) = 511.5 exactly
#define S_OFF 511.5f

#define THREADS 512
#define ELEMS_PER_THREAD 2

__device__ __forceinline__ float wz(const float* __restrict__ w, int c) {
    int ca = min(max(c, 0), NW - 1);
    float v = __ldg(w + ca);
    return (c >= 0 && c < NW) ? v : 0.0f;
}

__global__ __launch_bounds__(THREADS) void bspline_act_kernel(
    const float* __restrict__ x,
    const float* __restrict__ w,
    float* __restrict__ out,
    int n)
{
    __shared__ float  s_knot[NKNOT];          // 4 KB, bit-exact replica of reference knots
    __shared__ float4 s_coef[NKNOT - 1];      // 16 KB, per-interval cubic coefficients

    const int tid = threadIdx.x;

    // ---- prologue: knots (np.linspace in fp64, then fp32 cast; endpoint pinned) ----
    {
        const double start = -3.141592653589793;
        const double stop  =  3.141592653589793;
        const double step  = (stop - start) / 1023.0;
#pragma unroll
        for (int j = tid; j < NKNOT; j += THREADS) {
            double m = (double)j * step;      // rounded f64 multiply (matches numpy)
            float  f = (float)(m + start);    // rounded f64 add, then f32 cast
            if (j == NKNOT - 1) f = (float)stop;
            s_knot[j] = f;
        }
    }

    // ---- prologue: per-interval blend coefficients from weights ----
#pragma unroll
    for (int i = tid; i < NKNOT - 1; i += THREADS) {
        float w0 = wz(w, i - 3);
        float w1 = wz(w, i - 2);
        float w2 = wz(w, i - 1);
        float w3 = wz(w, i    );
        const float SIXTH = 0.16666666666666666f;
        float a = (w0 + 4.0f * w1 + w2) * SIXTH;
        float b = (w2 - w0) * 0.5f;
        float c = (w0 - 2.0f * w1 + w2) * 0.5f;
        float d = (w3 - w0) * SIXTH + (w1 - w2) * 0.5f;
        s_coef[i] = make_float4(a, b, c, d);
    }
    __syncthreads();

    // ---- main: 2 elements per thread ----
    int base = (blockIdx.x * THREADS + tid) * ELEMS_PER_THREAD;
    if (base >= n) return;

    float2 xv = *reinterpret_cast<const float2*>(x + base);
    float xs[2] = {xv.x, xv.y};
    float r[2];

#pragma unroll
    for (int e = 0; e < 2; e++) {
        float xx = xs[e];
        float s = fmaf(xx, INV_H, S_OFF);
        int i = (int)s;
        i = min(max(i, 0), NKNOT - 2);

        float  ti = s_knot[i];
        float4 cf = s_coef[i];
        float  u  = (xx - ti) * INV_H;

        float res = fmaf(fmaf(fmaf(cf.w, u, cf.z), u, cf.y), u, cf.x);
        bool in = (xx >= T_LO) && (xx < T_HI);
        r[e] = in ? res : 0.0f;
    }

    *reinterpret_cast<float2*>(out + base) = make_float2(r[0], r[1]);
}

extern "C" void kernel_launch(void* const* d_in, const int* in_sizes, int n_in,
                              void* d_out, int out_size) {
    const float* x = (const float*)d_in[0];
    const float* w = (const float*)d_in[1];
    float* out = (float*)d_out;
    int n = in_sizes[0];                                  // 262144
    int per_block = THREADS * ELEMS_PER_THREAD;
    int blocks = (n + per_block - 1) / per_block;         // 256
    bspline_act_kernel<<<blocks, THREADS>>>(x, w, out, n);
}